// round 1
// baseline (speedup 1.0000x reference)
#include <cuda_runtime.h>
#include <math_constants.h>

// ChamferLoss: B=8, N=8192, D=3.
// loss = sum_j min_i ||gts_i - preds_j||^2  +  sum_i min_j ||gts_i - preds_j||^2
// Strategy: one kernel, grid.z = direction (0: query=preds/ref=gts, 1: query=gts/ref=preds).
// Each thread owns one query point, scans all 8192 ref points via shared-memory
// float4 tiles (x,y,z,||r||^2). d = ||r||^2 - 2*dot(q,r); add ||q||^2 after the min.

#define NPTS    8192
#define BATCH   8
#define THREADS 256
#define CHUNK   1024
#define TILES   (NPTS / THREADS)   // 32

__global__ void chamfer_zero_kernel(float* out) {
    out[0] = 0.0f;
}

__global__ __launch_bounds__(THREADS)
void chamfer_min_kernel(const float* __restrict__ preds,
                        const float* __restrict__ gts,
                        float* __restrict__ out) {
    __shared__ float4 sref[CHUNK];
    __shared__ float  sred[THREADS];

    const int b   = blockIdx.y;
    const int dir = blockIdx.z;
    const float* query = (dir == 0) ? preds : gts;
    const float* ref   = (dir == 0) ? gts   : preds;

    const int i = blockIdx.x * THREADS + threadIdx.x;
    const float* qp = query + ((size_t)b * NPTS + i) * 3;
    const float qx = qp[0];
    const float qy = qp[1];
    const float qz = qp[2];
    const float qs = qx * qx + qy * qy + qz * qz;

    float m0 = CUDART_INF_F, m1 = CUDART_INF_F;
    float m2 = CUDART_INF_F, m3 = CUDART_INF_F;

    for (int c = 0; c < NPTS; c += CHUNK) {
        __syncthreads();
        // Cooperative load of CHUNK ref points -> shared float4 (x,y,z,norm2)
        #pragma unroll
        for (int k = threadIdx.x; k < CHUNK; k += THREADS) {
            const float* rp = ref + ((size_t)b * NPTS + c + k) * 3;
            const float rx = rp[0];
            const float ry = rp[1];
            const float rz = rp[2];
            sref[k] = make_float4(rx, ry, rz, rx * rx + ry * ry + rz * rz);
        }
        __syncthreads();

        #pragma unroll 2
        for (int j = 0; j < CHUNK; j += 4) {
            const float4 r0 = sref[j + 0];
            const float4 r1 = sref[j + 1];
            const float4 r2 = sref[j + 2];
            const float4 r3 = sref[j + 3];

            const float d0 = fmaf(-2.0f, fmaf(qx, r0.x, fmaf(qy, r0.y, qz * r0.z)), r0.w);
            const float d1 = fmaf(-2.0f, fmaf(qx, r1.x, fmaf(qy, r1.y, qz * r1.z)), r1.w);
            const float d2 = fmaf(-2.0f, fmaf(qx, r2.x, fmaf(qy, r2.y, qz * r2.z)), r2.w);
            const float d3 = fmaf(-2.0f, fmaf(qx, r3.x, fmaf(qy, r3.y, qz * r3.z)), r3.w);

            m0 = fminf(m0, d0);
            m1 = fminf(m1, d1);
            m2 = fminf(m2, d2);
            m3 = fminf(m3, d3);
        }
    }

    const float m = fminf(fminf(m0, m1), fminf(m2, m3)) + qs;

    // Block reduction (sum of per-query mins), then one atomicAdd per block.
    sred[threadIdx.x] = m;
    __syncthreads();
    #pragma unroll
    for (int s = THREADS / 2; s > 32; s >>= 1) {
        if (threadIdx.x < s) sred[threadIdx.x] += sred[threadIdx.x + s];
        __syncthreads();
    }
    if (threadIdx.x < 32) {
        float v = sred[threadIdx.x] + sred[threadIdx.x + 32];
        #pragma unroll
        for (int o = 16; o > 0; o >>= 1)
            v += __shfl_down_sync(0xffffffffu, v, o);
        if (threadIdx.x == 0) atomicAdd(out, v);
    }
}

extern "C" void kernel_launch(void* const* d_in, const int* in_sizes, int n_in,
                              void* d_out, int out_size) {
    const float* preds = (const float*)d_in[0];
    const float* gts   = (const float*)d_in[1];
    float* out = (float*)d_out;

    chamfer_zero_kernel<<<1, 1>>>(out);

    dim3 grid(TILES, BATCH, 2);
    chamfer_min_kernel<<<grid, THREADS>>>(preds, gts, out);
}

// round 2
// speedup vs baseline: 1.6586x; 1.6586x over previous
#include <cuda_runtime.h>
#include <math_constants.h>

// ChamferLoss B=8, N=8192, D=3.
// Kernel 1: register-tiled (Q=8 queries/thread) scan over ref slices with
//           packed f32x2 FMA (2 refs per instruction). Ref dim split 4 ways
//           for occupancy; per-query partial mins go to __device__ scratch.
// Kernel 2: min over the 4 ref-slices + global sum.

#define NPTS     8192
#define BATCH    8
#define THREADS  256
#define Q        8
#define SPLITS   4
#define REFS_PER_SPLIT (NPTS / SPLITS)   // 2048
#define CHUNK    1024                    // refs per smem tile
#define QTILES   (NPTS / (THREADS * Q))  // 4
#define FLAT     (2 * BATCH * NPTS)      // 131072 query slots

__device__ float g_partial[SPLITS][FLAT];

typedef unsigned long long ull;

__device__ __forceinline__ ull pack2(float a, float b) {
    ull r;
    asm("mov.b64 %0, {%1, %2};" : "=l"(r) : "f"(a), "f"(b));
    return r;
}
__device__ __forceinline__ ull mul2(ull a, ull b) {
    ull r;
    asm("mul.rn.f32x2 %0, %1, %2;" : "=l"(r) : "l"(a), "l"(b));
    return r;
}
__device__ __forceinline__ ull fma2(ull a, ull b, ull c) {
    ull r;
    asm("fma.rn.f32x2 %0, %1, %2, %3;" : "=l"(r) : "l"(a), "l"(b), "l"(c));
    return r;
}
__device__ __forceinline__ void unpack2(ull v, float& lo, float& hi) {
    unsigned int l, h;
    asm("mov.b64 {%0, %1}, %2;" : "=r"(l), "=r"(h) : "l"(v));
    lo = __uint_as_float(l);
    hi = __uint_as_float(h);
}

__global__ void chamfer_zero_kernel(float* out) { out[0] = 0.0f; }

__global__ __launch_bounds__(THREADS)
void chamfer_partial_kernel(const float* __restrict__ preds,
                            const float* __restrict__ gts) {
    // Packed SoA ref tile: each entry holds 2 consecutive refs' component.
    __shared__ ull sx2[CHUNK / 2];
    __shared__ ull sy2[CHUNK / 2];
    __shared__ ull sz2[CHUNK / 2];
    __shared__ ull sw2[CHUNK / 2];

    const int b   = blockIdx.y;
    const int z   = blockIdx.z;
    const int dir = z >> 2;        // 0: query=preds ref=gts ; 1: query=gts ref=preds
    const int s   = z & 3;         // ref slice
    const float* query = (dir == 0) ? preds : gts;
    const float* ref   = (dir == 0) ? gts   : preds;

    const int tid   = threadIdx.x;
    const int qbase = blockIdx.x * (THREADS * Q);

    ull   qx2[Q], qy2[Q], qz2[Q];
    float qs[Q], m[Q];
    int   qidx[Q];

    #pragma unroll
    for (int q = 0; q < Q; q++) {
        const int i = qbase + q * THREADS + tid;
        qidx[q] = i;
        const float* qp = query + ((size_t)b * NPTS + i) * 3;
        const float qx = qp[0], qy = qp[1], qz = qp[2];
        qx2[q] = pack2(qx, qx);
        qy2[q] = pack2(qy, qy);
        qz2[q] = pack2(qz, qz);
        qs[q]  = qx * qx + qy * qy + qz * qz;
        m[q]   = CUDART_INF_F;
    }

    const ull n2 = pack2(-2.0f, -2.0f);

    for (int c = 0; c < REFS_PER_SPLIT; c += CHUNK) {
        __syncthreads();
        float* sx = (float*)sx2;
        float* sy = (float*)sy2;
        float* sz = (float*)sz2;
        float* sw = (float*)sw2;
        const int rbase = s * REFS_PER_SPLIT + c;
        #pragma unroll
        for (int k = tid; k < CHUNK; k += THREADS) {
            const float* rp = ref + ((size_t)b * NPTS + rbase + k) * 3;
            const float rx = rp[0], ry = rp[1], rz = rp[2];
            sx[k] = rx;
            sy[k] = ry;
            sz[k] = rz;
            sw[k] = rx * rx + ry * ry + rz * rz;
        }
        __syncthreads();

        #pragma unroll 2
        for (int j = 0; j < CHUNK / 2; j++) {
            const ull rx = sx2[j];
            const ull ry = sy2[j];
            const ull rz = sz2[j];
            const ull rw = sw2[j];
            #pragma unroll
            for (int q = 0; q < Q; q++) {
                ull t = mul2(qz2[q], rz);
                t = fma2(qy2[q], ry, t);
                t = fma2(qx2[q], rx, t);
                const ull d = fma2(n2, t, rw);   // rw - 2*dot, for 2 refs
                float d0, d1;
                unpack2(d, d0, d1);
                m[q] = fminf(m[q], fminf(d0, d1));
            }
        }
    }

    #pragma unroll
    for (int q = 0; q < Q; q++) {
        const int flat = (dir * BATCH + b) * NPTS + qidx[q];
        g_partial[s][flat] = m[q] + qs[q];
    }
}

__global__ __launch_bounds__(THREADS)
void chamfer_reduce_kernel(float* __restrict__ out) {
    __shared__ float sred[THREADS];
    const int idx = blockIdx.x * THREADS + threadIdx.x;  // 0..FLAT-1

    const float v = fminf(fminf(g_partial[0][idx], g_partial[1][idx]),
                          fminf(g_partial[2][idx], g_partial[3][idx]));

    sred[threadIdx.x] = v;
    __syncthreads();
    #pragma unroll
    for (int sft = THREADS / 2; sft > 32; sft >>= 1) {
        if (threadIdx.x < sft) sred[threadIdx.x] += sred[threadIdx.x + sft];
        __syncthreads();
    }
    if (threadIdx.x < 32) {
        float r = sred[threadIdx.x] + sred[threadIdx.x + 32];
        #pragma unroll
        for (int o = 16; o > 0; o >>= 1)
            r += __shfl_down_sync(0xffffffffu, r, o);
        if (threadIdx.x == 0) atomicAdd(out, r);
    }
}

extern "C" void kernel_launch(void* const* d_in, const int* in_sizes, int n_in,
                              void* d_out, int out_size) {
    const float* preds = (const float*)d_in[0];
    const float* gts   = (const float*)d_in[1];
    float* out = (float*)d_out;

    chamfer_zero_kernel<<<1, 1>>>(out);

    dim3 grid1(QTILES, BATCH, 2 * SPLITS);   // (4, 8, 8) = 256 blocks
    chamfer_partial_kernel<<<grid1, THREADS>>>(preds, gts);

    chamfer_reduce_kernel<<<FLAT / THREADS, THREADS>>>(out);
}

// round 3
// speedup vs baseline: 1.7457x; 1.0525x over previous
#include <cuda_runtime.h>
#include <math_constants.h>

// ChamferLoss B=8, N=8192, D=3.
// R3: 1024 small blocks (128 thr, Q=8 queries/thread, 8 ref-slices) for
// single-wave load balance. f32x2 packs 2 QUERIES per lane; refs stored
// duplicated (r,r) in shared so LDS.64 yields packed operands directly.

#define NPTS     8192
#define BATCH    8
#define THREADS  128
#define Q        8                        // queries per thread
#define QPAIRS   (Q / 2)                  // 4 packed query pairs
#define SPLITS   8
#define REFS_PER_SPLIT (NPTS / SPLITS)    // 1024
#define CHUNK    512                      // refs per smem tile
#define QTILES   (NPTS / (THREADS * Q))   // 8
#define FLAT     (2 * BATCH * NPTS)       // 131072

__device__ float g_partial[SPLITS][FLAT];

typedef unsigned long long ull;

__device__ __forceinline__ ull pack2(float a, float b) {
    ull r;
    asm("mov.b64 %0, {%1, %2};" : "=l"(r) : "f"(a), "f"(b));
    return r;
}
__device__ __forceinline__ ull mul2(ull a, ull b) {
    ull r;
    asm("mul.rn.f32x2 %0, %1, %2;" : "=l"(r) : "l"(a), "l"(b));
    return r;
}
__device__ __forceinline__ ull fma2(ull a, ull b, ull c) {
    ull r;
    asm("fma.rn.f32x2 %0, %1, %2, %3;" : "=l"(r) : "l"(a), "l"(b), "l"(c));
    return r;
}
__device__ __forceinline__ void unpack2(ull v, float& lo, float& hi) {
    unsigned int l, h;
    asm("mov.b64 {%0, %1}, %2;" : "=r"(l), "=r"(h) : "l"(v));
    lo = __uint_as_float(l);
    hi = __uint_as_float(h);
}

__global__ void chamfer_zero_kernel(float* out) { out[0] = 0.0f; }

__global__ __launch_bounds__(THREADS, 7)
void chamfer_partial_kernel(const float* __restrict__ preds,
                            const float* __restrict__ gts) {
    // Duplicated ref tiles: entry k holds (v, v) for ref point k.
    __shared__ ull sx[CHUNK];
    __shared__ ull sy[CHUNK];
    __shared__ ull sz[CHUNK];
    __shared__ ull sw[CHUNK];

    const int b   = blockIdx.y;
    const int z   = blockIdx.z;
    const int dir = z >> 3;        // 0: query=preds ref=gts ; 1: query=gts ref=preds
    const int s   = z & 7;         // ref slice (1024 refs)
    const float* query = (dir == 0) ? preds : gts;
    const float* ref   = (dir == 0) ? gts   : preds;

    const int tid   = threadIdx.x;
    const int qbase = blockIdx.x * (THREADS * Q);

    // Packed query pairs: lane-lo = query (2p), lane-hi = query (2p+1).
    ull qx2[QPAIRS], qy2[QPAIRS], qz2[QPAIRS];
    float m[Q];

    #pragma unroll
    for (int p = 0; p < QPAIRS; p++) {
        const int ia = qbase + (2 * p)     * THREADS + tid;
        const int ib = qbase + (2 * p + 1) * THREADS + tid;
        const float* qa = query + ((size_t)b * NPTS + ia) * 3;
        const float* qb = query + ((size_t)b * NPTS + ib) * 3;
        qx2[p] = pack2(qa[0], qb[0]);
        qy2[p] = pack2(qa[1], qb[1]);
        qz2[p] = pack2(qa[2], qb[2]);
        m[2 * p]     = CUDART_INF_F;
        m[2 * p + 1] = CUDART_INF_F;
    }

    const ull n2 = pack2(-2.0f, -2.0f);

    for (int c = 0; c < REFS_PER_SPLIT; c += CHUNK) {
        __syncthreads();
        const int rbase = s * REFS_PER_SPLIT + c;
        #pragma unroll
        for (int k = tid; k < CHUNK; k += THREADS) {
            const float* rp = ref + ((size_t)b * NPTS + rbase + k) * 3;
            const float rx = rp[0], ry = rp[1], rz = rp[2];
            sx[k] = pack2(rx, rx);
            sy[k] = pack2(ry, ry);
            sz[k] = pack2(rz, rz);
            sw[k] = pack2(rx * rx + ry * ry + rz * rz,
                          rx * rx + ry * ry + rz * rz);
        }
        __syncthreads();

        #pragma unroll 4
        for (int j = 0; j < CHUNK; j++) {
            const ull rx = sx[j];
            const ull ry = sy[j];
            const ull rz = sz[j];
            const ull rw = sw[j];
            #pragma unroll
            for (int p = 0; p < QPAIRS; p++) {
                ull t = mul2(qz2[p], rz);
                t = fma2(qy2[p], ry, t);
                t = fma2(qx2[p], rx, t);
                const ull d = fma2(n2, t, rw);   // ||r||^2 - 2<q,r>, 2 queries
                float d0, d1;
                unpack2(d, d0, d1);
                m[2 * p]     = fminf(m[2 * p],     d0);
                m[2 * p + 1] = fminf(m[2 * p + 1], d1);
            }
        }
    }

    #pragma unroll
    for (int p = 0; p < QPAIRS; p++) {
        #pragma unroll
        for (int h = 0; h < 2; h++) {
            const int q = 2 * p + h;
            const int i = qbase + q * THREADS + tid;
            const float* qp = query + ((size_t)b * NPTS + i) * 3;
            const float qs = qp[0] * qp[0] + qp[1] * qp[1] + qp[2] * qp[2];
            const int flat = (dir * BATCH + b) * NPTS + i;
            g_partial[s][flat] = m[q] + qs;
        }
    }
}

__global__ __launch_bounds__(256)
void chamfer_reduce_kernel(float* __restrict__ out) {
    __shared__ float sred[256];
    const int idx = blockIdx.x * 256 + threadIdx.x;  // 0..FLAT-1

    float v = g_partial[0][idx];
    #pragma unroll
    for (int s = 1; s < SPLITS; s++) v = fminf(v, g_partial[s][idx]);

    sred[threadIdx.x] = v;
    __syncthreads();
    #pragma unroll
    for (int sft = 128; sft > 32; sft >>= 1) {
        if (threadIdx.x < sft) sred[threadIdx.x] += sred[threadIdx.x + sft];
        __syncthreads();
    }
    if (threadIdx.x < 32) {
        float r = sred[threadIdx.x] + sred[threadIdx.x + 32];
        #pragma unroll
        for (int o = 16; o > 0; o >>= 1)
            r += __shfl_down_sync(0xffffffffu, r, o);
        if (threadIdx.x == 0) atomicAdd(out, r);
    }
}

extern "C" void kernel_launch(void* const* d_in, const int* in_sizes, int n_in,
                              void* d_out, int out_size) {
    const float* preds = (const float*)d_in[0];
    const float* gts   = (const float*)d_in[1];
    float* out = (float*)d_out;

    chamfer_zero_kernel<<<1, 1>>>(out);

    dim3 grid1(QTILES, BATCH, 2 * SPLITS);   // (8, 8, 16) = 1024 blocks
    chamfer_partial_kernel<<<grid1, THREADS>>>(preds, gts);

    chamfer_reduce_kernel<<<FLAT / 256, 256>>>(out);
}

// round 4
// speedup vs baseline: 1.7553x; 1.0055x over previous
#include <cuda_runtime.h>
#include <math_constants.h>

// ChamferLoss B=8, N=8192, D=3.
// R4: 3-FMA packed chain (q' = -2q prescaled):
//     d = fma2(qx',rx, fma2(qy',ry, fma2(qz',rz, rw)))  for 2 queries/lane.
// Zero-kernel folded into the partial kernel. 1024 blocks, single wave.

#define NPTS     8192
#define BATCH    8
#define THREADS  128
#define Q        8                        // queries per thread
#define QPAIRS   (Q / 2)                  // 4 packed query pairs
#define SPLITS   8
#define REFS_PER_SPLIT (NPTS / SPLITS)    // 1024
#define CHUNK    512                      // refs per smem tile
#define QTILES   (NPTS / (THREADS * Q))   // 8
#define FLAT     (2 * BATCH * NPTS)       // 131072

__device__ float g_partial[SPLITS][FLAT];

typedef unsigned long long ull;

__device__ __forceinline__ ull pack2(float a, float b) {
    ull r;
    asm("mov.b64 %0, {%1, %2};" : "=l"(r) : "f"(a), "f"(b));
    return r;
}
__device__ __forceinline__ ull fma2(ull a, ull b, ull c) {
    ull r;
    asm("fma.rn.f32x2 %0, %1, %2, %3;" : "=l"(r) : "l"(a), "l"(b), "l"(c));
    return r;
}
__device__ __forceinline__ void unpack2(ull v, float& lo, float& hi) {
    unsigned int l, h;
    asm("mov.b64 {%0, %1}, %2;" : "=r"(l), "=r"(h) : "l"(v));
    lo = __uint_as_float(l);
    hi = __uint_as_float(h);
}

__global__ __launch_bounds__(THREADS, 7)
void chamfer_partial_kernel(const float* __restrict__ preds,
                            const float* __restrict__ gts,
                            float* __restrict__ out) {
    // Duplicated ref tiles: entry k holds (v, v) for ref point k.
    __shared__ ull sx[CHUNK];
    __shared__ ull sy[CHUNK];
    __shared__ ull sz[CHUNK];
    __shared__ ull sw[CHUNK];

    // Zero the output once; only the (later) reduce kernel touches out.
    if (blockIdx.x == 0 && blockIdx.y == 0 && blockIdx.z == 0 &&
        threadIdx.x == 0) {
        out[0] = 0.0f;
    }

    const int b   = blockIdx.y;
    const int z   = blockIdx.z;
    const int dir = z >> 3;        // 0: query=preds ref=gts ; 1: query=gts ref=preds
    const int s   = z & 7;         // ref slice (1024 refs)
    const float* query = (dir == 0) ? preds : gts;
    const float* ref   = (dir == 0) ? gts   : preds;

    const int tid   = threadIdx.x;
    const int qbase = blockIdx.x * (THREADS * Q);

    // Packed query pairs, prescaled by -2: lane-lo = q(2p), lane-hi = q(2p+1).
    ull qx2[QPAIRS], qy2[QPAIRS], qz2[QPAIRS];
    float qs[Q], m[Q];

    #pragma unroll
    for (int p = 0; p < QPAIRS; p++) {
        const int ia = qbase + (2 * p)     * THREADS + tid;
        const int ib = qbase + (2 * p + 1) * THREADS + tid;
        const float* qa = query + ((size_t)b * NPTS + ia) * 3;
        const float* qb = query + ((size_t)b * NPTS + ib) * 3;
        const float ax = qa[0], ay = qa[1], az = qa[2];
        const float bx = qb[0], by = qb[1], bz = qb[2];
        qx2[p] = pack2(-2.0f * ax, -2.0f * bx);
        qy2[p] = pack2(-2.0f * ay, -2.0f * by);
        qz2[p] = pack2(-2.0f * az, -2.0f * bz);
        qs[2 * p]     = ax * ax + ay * ay + az * az;
        qs[2 * p + 1] = bx * bx + by * by + bz * bz;
        m[2 * p]     = CUDART_INF_F;
        m[2 * p + 1] = CUDART_INF_F;
    }

    for (int c = 0; c < REFS_PER_SPLIT; c += CHUNK) {
        __syncthreads();
        const int rbase = s * REFS_PER_SPLIT + c;
        #pragma unroll
        for (int k = tid; k < CHUNK; k += THREADS) {
            const float* rp = ref + ((size_t)b * NPTS + rbase + k) * 3;
            const float rx = rp[0], ry = rp[1], rz = rp[2];
            const float rn = rx * rx + ry * ry + rz * rz;
            sx[k] = pack2(rx, rx);
            sy[k] = pack2(ry, ry);
            sz[k] = pack2(rz, rz);
            sw[k] = pack2(rn, rn);
        }
        __syncthreads();

        #pragma unroll 4
        for (int j = 0; j < CHUNK; j++) {
            const ull rx = sx[j];
            const ull ry = sy[j];
            const ull rz = sz[j];
            const ull rw = sw[j];
            #pragma unroll
            for (int p = 0; p < QPAIRS; p++) {
                ull t = fma2(qz2[p], rz, rw);
                t = fma2(qy2[p], ry, t);
                t = fma2(qx2[p], rx, t);   // ||r||^2 - 2<q,r> for 2 queries
                float d0, d1;
                unpack2(t, d0, d1);
                m[2 * p]     = fminf(m[2 * p],     d0);
                m[2 * p + 1] = fminf(m[2 * p + 1], d1);
            }
        }
    }

    #pragma unroll
    for (int q = 0; q < Q; q++) {
        const int i = qbase + q * THREADS + tid;
        const int flat = (dir * BATCH + b) * NPTS + i;
        g_partial[s][flat] = m[q] + qs[q];
    }
}

__global__ __launch_bounds__(256)
void chamfer_reduce_kernel(float* __restrict__ out) {
    __shared__ float sred[256];
    const int idx = blockIdx.x * 256 + threadIdx.x;  // 0..FLAT-1

    float v = g_partial[0][idx];
    #pragma unroll
    for (int s = 1; s < SPLITS; s++) v = fminf(v, g_partial[s][idx]);

    sred[threadIdx.x] = v;
    __syncthreads();
    #pragma unroll
    for (int sft = 128; sft > 32; sft >>= 1) {
        if (threadIdx.x < sft) sred[threadIdx.x] += sred[threadIdx.x + sft];
        __syncthreads();
    }
    if (threadIdx.x < 32) {
        float r = sred[threadIdx.x] + sred[threadIdx.x + 32];
        #pragma unroll
        for (int o = 16; o > 0; o >>= 1)
            r += __shfl_down_sync(0xffffffffu, r, o);
        if (threadIdx.x == 0) atomicAdd(out, r);
    }
}

extern "C" void kernel_launch(void* const* d_in, const int* in_sizes, int n_in,
                              void* d_out, int out_size) {
    const float* preds = (const float*)d_in[0];
    const float* gts   = (const float*)d_in[1];
    float* out = (float*)d_out;

    dim3 grid1(QTILES, BATCH, 2 * SPLITS);   // (8, 8, 16) = 1024 blocks
    chamfer_partial_kernel<<<grid1, THREADS>>>(preds, gts, out);

    chamfer_reduce_kernel<<<FLAT / 256, 256>>>(out);
}

// round 5
// speedup vs baseline: 2.1880x; 1.2465x over previous
#include <cuda_runtime.h>
#include <math_constants.h>

// ChamferLoss B=8, N=8192, D=3.
// R5: refs streamed as NON-duplicated pairs (r2k, r2k+1) packed per component
// in shared (2x LDS.128 per 2 refs); queries duplicated (q,q), prescaled -2q,
// held in registers. d = fma2(qx',rx2, fma2(qy',ry2, fma2(qz',rz2, rw2))).

#define NPTS     8192
#define BATCH    8
#define THREADS  128
#define Q        8                        // queries per thread
#define SPLITS   8
#define REFS_PER_SPLIT (NPTS / SPLITS)    // 1024
#define PAIRS    (REFS_PER_SPLIT / 2)     // 512 ref-pairs per slice
#define QTILES   (NPTS / (THREADS * Q))   // 8
#define FLAT     (2 * BATCH * NPTS)       // 131072

__device__ float g_partial[SPLITS][FLAT];

typedef unsigned long long ull;

struct __align__(16) RefQuad {
    ull x, y, z, w;   // (r0.x,r1.x) (r0.y,r1.y) (r0.z,r1.z) (n0,n1)
};

__device__ __forceinline__ ull pack2(float a, float b) {
    ull r;
    asm("mov.b64 %0, {%1, %2};" : "=l"(r) : "f"(a), "f"(b));
    return r;
}
__device__ __forceinline__ ull fma2(ull a, ull b, ull c) {
    ull r;
    asm("fma.rn.f32x2 %0, %1, %2, %3;" : "=l"(r) : "l"(a), "l"(b), "l"(c));
    return r;
}
__device__ __forceinline__ void unpack2(ull v, float& lo, float& hi) {
    unsigned int l, h;
    asm("mov.b64 {%0, %1}, %2;" : "=r"(l), "=r"(h) : "l"(v));
    lo = __uint_as_float(l);
    hi = __uint_as_float(h);
}

__global__ __launch_bounds__(THREADS, 6)
void chamfer_partial_kernel(const float* __restrict__ preds,
                            const float* __restrict__ gts,
                            float* __restrict__ out) {
    __shared__ RefQuad sref[PAIRS];   // 512 * 32B = 16KB

    if (blockIdx.x == 0 && blockIdx.y == 0 && blockIdx.z == 0 &&
        threadIdx.x == 0) {
        out[0] = 0.0f;   // only the later reduce kernel touches out
    }

    const int b   = blockIdx.y;
    const int z   = blockIdx.z;
    const int dir = z >> 3;        // 0: query=preds ref=gts ; 1: query=gts ref=preds
    const int s   = z & 7;         // ref slice (1024 refs)
    const float* query = (dir == 0) ? preds : gts;
    const float* ref   = (dir == 0) ? gts   : preds;

    const int tid   = threadIdx.x;
    const int qbase = blockIdx.x * (THREADS * Q);

    // Queries duplicated (q,q), prescaled by -2.
    ull qx2[Q], qy2[Q], qz2[Q];
    float m[Q];

    #pragma unroll
    for (int q = 0; q < Q; q++) {
        const int i = qbase + q * THREADS + tid;
        const float* qp = query + ((size_t)b * NPTS + i) * 3;
        const float x = -2.0f * qp[0];
        const float y = -2.0f * qp[1];
        const float zc = -2.0f * qp[2];
        qx2[q] = pack2(x, x);
        qy2[q] = pack2(y, y);
        qz2[q] = pack2(zc, zc);
        m[q] = CUDART_INF_F;
    }

    // Load the whole 1024-ref slice as 512 component-packed pairs.
    {
        const int rbase = s * REFS_PER_SPLIT;
        #pragma unroll
        for (int k = tid; k < PAIRS; k += THREADS) {
            const float* rp = ref + ((size_t)b * NPTS + rbase + 2 * k) * 3;
            const float2 v0 = *(const float2*)(rp + 0);   // r0.x r0.y
            const float2 v1 = *(const float2*)(rp + 2);   // r0.z r1.x
            const float2 v2 = *(const float2*)(rp + 4);   // r1.y r1.z
            const float n0 = v0.x * v0.x + v0.y * v0.y + v1.x * v1.x;
            const float n1 = v1.y * v1.y + v2.x * v2.x + v2.y * v2.y;
            RefQuad rq;
            rq.x = pack2(v0.x, v1.y);
            rq.y = pack2(v0.y, v2.x);
            rq.z = pack2(v1.x, v2.y);
            rq.w = pack2(n0, n1);
            sref[k] = rq;
        }
    }
    __syncthreads();

    #pragma unroll 2
    for (int j = 0; j < PAIRS; j++) {
        const ulonglong2 pxy = *(const ulonglong2*)(&sref[j].x);
        const ulonglong2 pzw = *(const ulonglong2*)(&sref[j].z);
        #pragma unroll
        for (int q = 0; q < Q; q++) {
            ull t = fma2(qz2[q], pzw.x, pzw.y);
            t = fma2(qy2[q], pxy.y, t);
            t = fma2(qx2[q], pxy.x, t);   // (||r0||^2-2<q,r0>, ||r1||^2-2<q,r1>)
            float d0, d1;
            unpack2(t, d0, d1);
            m[q] = fminf(m[q], fminf(d0, d1));
        }
    }

    #pragma unroll
    for (int q = 0; q < Q; q++) {
        float hx, hy, hz, dummy;
        unpack2(qx2[q], hx, dummy);
        unpack2(qy2[q], hy, dummy);
        unpack2(qz2[q], hz, dummy);
        const float qs = 0.25f * (hx * hx + hy * hy + hz * hz);  // (-2q)^2/4
        const int i = qbase + q * THREADS + tid;
        const int flat = (dir * BATCH + b) * NPTS + i;
        g_partial[s][flat] = m[q] + qs;
    }
}

__global__ __launch_bounds__(256)
void chamfer_reduce_kernel(float* __restrict__ out) {
    __shared__ float sred[256];
    const int idx = blockIdx.x * 256 + threadIdx.x;  // 0..FLAT-1

    float v = g_partial[0][idx];
    #pragma unroll
    for (int s = 1; s < SPLITS; s++) v = fminf(v, g_partial[s][idx]);

    sred[threadIdx.x] = v;
    __syncthreads();
    #pragma unroll
    for (int sft = 128; sft > 32; sft >>= 1) {
        if (threadIdx.x < sft) sred[threadIdx.x] += sred[threadIdx.x + sft];
        __syncthreads();
    }
    if (threadIdx.x < 32) {
        float r = sred[threadIdx.x] + sred[threadIdx.x + 32];
        #pragma unroll
        for (int o = 16; o > 0; o >>= 1)
            r += __shfl_down_sync(0xffffffffu, r, o);
        if (threadIdx.x == 0) atomicAdd(out, r);
    }
}

extern "C" void kernel_launch(void* const* d_in, const int* in_sizes, int n_in,
                              void* d_out, int out_size) {
    const float* preds = (const float*)d_in[0];
    const float* gts   = (const float*)d_in[1];
    float* out = (float*)d_out;

    dim3 grid1(QTILES, BATCH, 2 * SPLITS);   // (8, 8, 16) = 1024 blocks
    chamfer_partial_kernel<<<grid1, THREADS>>>(preds, gts, out);

    chamfer_reduce_kernel<<<FLAT / 256, 256>>>(out);
}